// round 12
// baseline (speedup 1.0000x reference)
#include <cuda_runtime.h>
#include <math.h>

#define T_TOKENS 16384
#define DIM      768
#define INTER    512
#define NE       8
#define NGROUP   4
#define CAP      16384

#define PITCH    20                    // words per 16-elt row: conflict-free ldsm/STS.128
#define ABUF_W   (128 * PITCH)         // 2560 words per A buffer (128 rows)
#define S1B_W    (128 * PITCH)         // 2560 words per stage1 B buffer
#define S2B_W    (256 * PITCH)         // 5120 words per stage2 B buffer

// ---------------- scratch (device globals; no allocations) ----------------
__device__ int   g_count[NE];
__device__ int   g_tok[NE * CAP];
__device__ float g_wt [NE * CAP];
__device__ float g_H[(size_t)(NE + 1) * CAP * INTER];

// ---------------- helpers ----------------
__device__ __forceinline__ unsigned f2tf32(float f) {
    unsigned r; asm("cvt.rna.tf32.f32 %0, %1;" : "=r"(r) : "f"(f)); return r;
}

__device__ __forceinline__ void mma_tf32(float (&d)[4], const unsigned* a,
                                         const unsigned* b) {
    asm volatile(
        "mma.sync.aligned.m16n8k8.row.col.f32.tf32.tf32.f32 "
        "{%0,%1,%2,%3}, {%4,%5,%6,%7}, {%8,%9}, {%0,%1,%2,%3};\n"
        : "+f"(d[0]), "+f"(d[1]), "+f"(d[2]), "+f"(d[3])
        : "r"(a[0]), "r"(a[1]), "r"(a[2]), "r"(a[3]), "r"(b[0]), "r"(b[1]));
}

__device__ __forceinline__ void ldsm4(unsigned& r0, unsigned& r1, unsigned& r2,
                                      unsigned& r3, unsigned addr) {
    asm volatile("ldmatrix.sync.aligned.m8n8.x4.shared.b16 {%0,%1,%2,%3}, [%4];"
                 : "=r"(r0), "=r"(r1), "=r"(r2), "=r"(r3) : "r"(addr));
}

__device__ __forceinline__ void cvt_sts128(unsigned* dst, float4 v) {
    uint4 u;
    u.x = f2tf32(v.x); u.y = f2tf32(v.y); u.z = f2tf32(v.z); u.w = f2tf32(v.w);
    *(uint4*)dst = u;
}

// ---------------- kernel 0: zero counters ----------------
__global__ void zero_counts_kernel() {
    if (threadIdx.x < NE) g_count[threadIdx.x] = 0;
}

// ---------------- kernel 1: gating (exact fp32) ----------------
__global__ void gate_kernel(const float* __restrict__ x,
                            const float* __restrict__ gw,
                            const float* __restrict__ gb) {
    int warp = threadIdx.x >> 5;
    int lane = threadIdx.x & 31;
    int t = blockIdx.x * 8 + warp;
    if (t >= T_TOKENS) return;

    float acc[NE];
#pragma unroll
    for (int e = 0; e < NE; e++) acc[e] = 0.f;

    const float* xr = x + (size_t)t * DIM;
    for (int j = lane; j < DIM; j += 32) {
        float xv = xr[j];
#pragma unroll
        for (int e = 0; e < NE; e++) acc[e] += xv * gw[e * DIM + j];
    }
#pragma unroll
    for (int off = 16; off > 0; off >>= 1) {
#pragma unroll
        for (int e = 0; e < NE; e++)
            acc[e] += __shfl_xor_sync(0xFFFFFFFF, acc[e], off);
    }

    if (lane == 0) {
        float sc[NE], sb[NE];
#pragma unroll
        for (int e = 0; e < NE; e++) {
            sc[e] = 1.f / (1.f + expf(-acc[e]));
            sb[e] = sc[e] + gb[e];
        }
        float gs[NGROUP];
#pragma unroll
        for (int g = 0; g < NGROUP; g++) gs[g] = sb[2 * g] + sb[2 * g + 1];
        int g1 = 0;
#pragma unroll
        for (int g = 1; g < NGROUP; g++) if (gs[g] > gs[g1]) g1 = g;
        int g2 = -1;
#pragma unroll
        for (int g = 0; g < NGROUP; g++) {
            if (g == g1) continue;
            if (g2 < 0 || gs[g] > gs[g2]) g2 = g;
        }
        int   b1 = -1, b2 = -1;
        float v1 = -1e30f, v2 = -1e30f;
#pragma unroll
        for (int e = 0; e < NE; e++) {
            int g = e >> 1;
            if (g != g1 && g != g2) continue;
            float v = sb[e];
            if (v > v1)      { v2 = v1; b2 = b1; v1 = v; b1 = e; }
            else if (v > v2) { v2 = v;  b2 = e; }
        }
        float wa = sc[b1], wb = sc[b2];
        float inv = 1.f / (wa + wb + 1e-6f);
        wa *= inv; wb *= inv;

        int s1 = atomicAdd(&g_count[b1], 1);
        g_tok[b1 * CAP + s1] = t;  g_wt[b1 * CAP + s1] = wa;
        int s2 = atomicAdd(&g_count[b2], 1);
        g_tok[b2 * CAP + s2] = t;  g_wt[b2 * CAP + s2] = wb;
    }
}

// ---------------- stage 1: H = silu(Xg w1^T) * (Xg w3^T) ----------------
// Block 128x128, BK=16, 8 warps (2x4); warp tile 64 rows x 32 cols per matrix.
// Dynamic smem (words): As[2*ABUF_W] | B1[2*S1B_W] | B3[2*S1B_W]  (61440 B)
__global__ __launch_bounds__(256)
void stage1_mma(const float* __restrict__ x,
                const float* __restrict__ w1,
                const float* __restrict__ w3,
                const float* __restrict__ sw1,
                const float* __restrict__ sw3) {
    const int e  = blockIdx.x >> 7;
    const int mt = blockIdx.x & 127;
    const int cnt = (e == NE) ? T_TOKENS : g_count[e];
    const int m0 = mt * 128;
    if (m0 >= cnt) return;
    const int n0 = blockIdx.y * 128;

    const float* W1 = (e < NE) ? w1 + (size_t)e * INTER * DIM : sw1;
    const float* W3 = (e < NE) ? w3 + (size_t)e * INTER * DIM : sw3;

    extern __shared__ unsigned smem[];
    unsigned* As = smem;
    unsigned* B1 = smem + 2 * ABUF_W;
    unsigned* B3 = smem + 2 * ABUF_W + 2 * S1B_W;
    const unsigned sbase = (unsigned)__cvta_generic_to_shared(smem);

    const int tid  = threadIdx.x;
    const int lane = tid & 31;
    const int wid  = tid >> 5;
    const int wm   = (wid >> 2) * 64;
    const int wn   = (wid & 3) * 32;

    // gmem->smem: 512 float4 per 128x16 tile, 2 per thread (idx = tid + s*256)
    int   arowi[2]; bool av[2]; const float* xA[2];
    int   sidx[2];
#pragma unroll
    for (int s = 0; s < 2; s++) {
        int idx  = tid + s * 256;
        int row  = idx >> 2;
        int kc   = (idx & 3) * 4;
        sidx[s]  = row * PITCH + kc;
        arowi[s] = row;
        av[s]    = (m0 + row) < cnt;
        int tok  = av[s] ? ((e == NE) ? (m0 + row) : g_tok[e * CAP + m0 + row]) : 0;
        xA[s]    = x + (size_t)tok * DIM + kc;
    }

    // ldmatrix base addresses (buffer0, ks0, tile i=0 / p=0)
    const unsigned a_addr0 = sbase +
        ((wm + ((lane >> 3) & 1) * 8 + (lane & 7)) * PITCH + (lane >> 4) * 4) * 4;
    const unsigned brow = wn + (lane >> 4) * 8 + (lane & 7);
    const unsigned bkc  = ((lane >> 3) & 1) * 4;
    const unsigned b1_addr0 = sbase + (2 * ABUF_W + brow * PITCH + bkc) * 4;
    const unsigned b3_addr0 = sbase + (2 * ABUF_W + 2 * S1B_W + brow * PITCH + bkc) * 4;

    float4 aR[2], b1R[2], b3R[2];
    const float4 Z4 = make_float4(0.f, 0.f, 0.f, 0.f);

#define S1_LOAD(k0)                                                            \
    {                                                                          \
        _Pragma("unroll")                                                      \
        for (int s = 0; s < 2; s++) {                                          \
            aR[s]  = av[s] ? *(const float4*)(xA[s] + (k0)) : Z4;              \
            int idx = tid + s * 256;                                           \
            int row = idx >> 2, kc = (idx & 3) * 4;                            \
            b1R[s] = *(const float4*)&W1[(size_t)(n0 + row) * DIM + (k0) + kc];\
            b3R[s] = *(const float4*)&W3[(size_t)(n0 + row) * DIM + (k0) + kc];\
        }                                                                      \
    }

#define S1_STORE(buf)                                                          \
    {                                                                          \
        _Pragma("unroll")                                                      \
        for (int s = 0; s < 2; s++) {                                          \
            cvt_sts128(As + (buf) * ABUF_W + sidx[s], aR[s]);                  \
            cvt_sts128(B1 + (buf) * S1B_W + sidx[s], b1R[s]);                  \
            cvt_sts128(B3 + (buf) * S1B_W + sidx[s], b3R[s]);                  \
        }                                                                      \
    }

    float acc1[4][4][4], acc3[4][4][4];
#pragma unroll
    for (int i = 0; i < 4; i++)
#pragma unroll
        for (int j = 0; j < 4; j++)
#pragma unroll
            for (int q = 0; q < 4; q++) { acc1[i][j][q] = 0.f; acc3[i][j][q] = 0.f; }

    const int NKT = DIM / 16;   // 48
    S1_LOAD(0);
    S1_STORE(0);
    __syncthreads();

    for (int kt = 0; kt < NKT; kt++) {
        const unsigned abuf = (kt & 1) * (ABUF_W * 4);
        const unsigned bbuf = (kt & 1) * (S1B_W * 4);
        if (kt + 1 < NKT) S1_LOAD((kt + 1) * 16);

#pragma unroll
        for (int ks = 0; ks < 2; ks++) {
            const unsigned ko = ks * 32;
            unsigned a[4][4];
#pragma unroll
            for (int i = 0; i < 4; i++)
                ldsm4(a[i][0], a[i][1], a[i][2], a[i][3],
                      a_addr0 + abuf + ko + i * (16 * PITCH * 4));
            unsigned b1r[8], b3r[8];
#pragma unroll
            for (int p = 0; p < 2; p++) {
                ldsm4(b1r[p*4], b1r[p*4+1], b1r[p*4+2], b1r[p*4+3],
                      b1_addr0 + bbuf + ko + p * (16 * PITCH * 4));
                ldsm4(b3r[p*4], b3r[p*4+1], b3r[p*4+2], b3r[p*4+3],
                      b3_addr0 + bbuf + ko + p * (16 * PITCH * 4));
            }
#pragma unroll
            for (int j = 0; j < 4; j++)
#pragma unroll
                for (int i = 0; i < 4; i++) {
                    mma_tf32(acc1[i][j], a[i], &b1r[j * 2]);
                    mma_tf32(acc3[i][j], a[i], &b3r[j * 2]);
                }
        }

        if (kt + 1 < NKT) S1_STORE((kt + 1) & 1);
        __syncthreads();
    }

    // epilogue: H = silu(h1) * h3
    const size_t hbase = (size_t)e * CAP * INTER;
    const int r  = lane >> 2;
    const int c2 = (lane & 3) * 2;
#pragma unroll
    for (int i = 0; i < 4; i++) {
#pragma unroll
        for (int half = 0; half < 2; half++) {
            int row = m0 + wm + i * 16 + r + half * 8;
            if (row < cnt) {
                float* hrow = &g_H[hbase + (size_t)row * INTER + n0 + wn + c2];
#pragma unroll
                for (int j = 0; j < 4; j++) {
                    float h1a = acc1[i][j][half * 2 + 0];
                    float h1b = acc1[i][j][half * 2 + 1];
                    float h3a = acc3[i][j][half * 2 + 0];
                    float h3b = acc3[i][j][half * 2 + 1];
                    float2 v;
                    v.x = (h1a / (1.f + __expf(-h1a))) * h3a;
                    v.y = (h1b / (1.f + __expf(-h1b))) * h3b;
                    *(float2*)&hrow[j * 8] = v;
                }
            }
        }
    }
#undef S1_LOAD
#undef S1_STORE
}

// ---------------- stage 2: out = (H_e w2^T) * cw ----------------
// Block 128x256, BK=16, 8 warps (2x4); warp tile 64x64.
// Dynamic smem (words): As[2*ABUF_W] | Bs[2*S2B_W]  (61440 B)
template <bool SHARED>
__global__ __launch_bounds__(256)
void stage2_mma(const float* __restrict__ w2,
                const float* __restrict__ sw2,
                float* __restrict__ out) {
    int e, mt;
    if (SHARED) { e = NE; mt = blockIdx.x; }
    else        { e = blockIdx.x >> 7; mt = blockIdx.x & 127; }
    const int cnt = SHARED ? T_TOKENS : g_count[e];
    const int m0 = mt * 128;
    if (m0 >= cnt) return;
    const int n0 = blockIdx.y * 256;

    const float* W  = SHARED ? sw2 : w2 + (size_t)e * DIM * INTER;
    const float* Hb = g_H + (size_t)e * CAP * INTER;

    extern __shared__ unsigned smem[];
    unsigned* As = smem;
    unsigned* Bs = smem + 2 * ABUF_W;
    const unsigned sbase = (unsigned)__cvta_generic_to_shared(smem);

    const int tid  = threadIdx.x;
    const int lane = tid & 31;
    const int wid  = tid >> 5;
    const int wm   = (wid >> 2) * 64;
    const int wn   = (wid & 3) * 64;

    // A: 128x16 -> 512 f4, 2/thread (rows are slot indices in g_H: no gather,
    // out-of-range rows read garbage but are masked at the epilogue).
    int a_sidx[2]; const float* hA[2];
#pragma unroll
    for (int s = 0; s < 2; s++) {
        int idx = tid + s * 256;
        int row = idx >> 2, kc = (idx & 3) * 4;
        a_sidx[s] = row * PITCH + kc;
        int rr = m0 + row; if (rr >= CAP) rr = CAP - 1;
        hA[s] = Hb + (size_t)rr * INTER + kc;
    }
    // B: 256x16 -> 1024 f4, 4/thread
    int b_sidx[4]; const float* wB[4];
#pragma unroll
    for (int s = 0; s < 4; s++) {
        int idx = tid + s * 256;
        int row = idx >> 2, kc = (idx & 3) * 4;
        b_sidx[s] = row * PITCH + kc;
        wB[s] = W + (size_t)(n0 + row) * INTER + kc;
    }

    const unsigned a_addr0 = sbase +
        ((wm + ((lane >> 3) & 1) * 8 + (lane & 7)) * PITCH + (lane >> 4) * 4) * 4;
    const unsigned brow = wn + (lane >> 4) * 8 + (lane & 7);
    const unsigned bkc  = ((lane >> 3) & 1) * 4;
    const unsigned b_addr0 = sbase + (2 * ABUF_W + brow * PITCH + bkc) * 4;

    float4 aR[2], bR[4];

#define S2_LOAD(k0)                                                            \
    {                                                                          \
        _Pragma("unroll")                                                      \
        for (int s = 0; s < 2; s++) aR[s] = *(const float4*)(hA[s] + (k0));    \
        _Pragma("unroll")                                                      \
        for (int s = 0; s < 4; s++) bR[s] = *(const float4*)(wB[s] + (k0));    \
    }

#define S2_STORE(buf)                                                          \
    {                                                                          \
        _Pragma("unroll")                                                      \
        for (int s = 0; s < 2; s++) cvt_sts128(As + (buf) * ABUF_W + a_sidx[s], aR[s]); \
        _Pragma("unroll")                                                      \
        for (int s = 0; s < 4; s++) cvt_sts128(Bs + (buf) * S2B_W + b_sidx[s], bR[s]);  \
    }

    float acc[4][8][4];
#pragma unroll
    for (int i = 0; i < 4; i++)
#pragma unroll
        for (int j = 0; j < 8; j++)
#pragma unroll
            for (int q = 0; q < 4; q++) acc[i][j][q] = 0.f;

    const int NKT = INTER / 16;   // 32
    S2_LOAD(0);
    S2_STORE(0);
    __syncthreads();

    for (int kt = 0; kt < NKT; kt++) {
        const unsigned abuf = (kt & 1) * (ABUF_W * 4);
        const unsigned bbuf = (kt & 1) * (S2B_W * 4);
        if (kt + 1 < NKT) S2_LOAD((kt + 1) * 16);

#pragma unroll
        for (int ks = 0; ks < 2; ks++) {
            const unsigned ko = ks * 32;
            unsigned a[4][4];
#pragma unroll
            for (int i = 0; i < 4; i++)
                ldsm4(a[i][0], a[i][1], a[i][2], a[i][3],
                      a_addr0 + abuf + ko + i * (16 * PITCH * 4));
            unsigned br[16];
#pragma unroll
            for (int p = 0; p < 4; p++)
                ldsm4(br[p*4], br[p*4+1], br[p*4+2], br[p*4+3],
                      b_addr0 + bbuf + ko + p * (16 * PITCH * 4));
#pragma unroll
            for (int j = 0; j < 8; j++)
#pragma unroll
                for (int i = 0; i < 4; i++)
                    mma_tf32(acc[i][j], a[i], &br[j * 2]);
        }

        if (kt + 1 < NKT) S2_STORE((kt + 1) & 1);
        __syncthreads();
    }

    const int r  = lane >> 2;
    const int c2 = (lane & 3) * 2;
#pragma unroll
    for (int i = 0; i < 4; i++) {
#pragma unroll
        for (int half = 0; half < 2; half++) {
            int row = m0 + wm + i * 16 + r + half * 8;
            if (row < cnt) {
                if (SHARED) {
                    float* orow = &out[(size_t)row * DIM + n0 + wn + c2];
#pragma unroll
                    for (int j = 0; j < 8; j++) {
                        float2 v;
                        v.x = acc[i][j][half * 2 + 0];
                        v.y = acc[i][j][half * 2 + 1];
                        *(float2*)&orow[j * 8] = v;
                    }
                } else {
                    int   t   = g_tok[e * CAP + row];
                    float wgt = g_wt [e * CAP + row];
                    float* orow = &out[(size_t)t * DIM + n0 + wn + c2];
#pragma unroll
                    for (int j = 0; j < 8; j++) {
                        atomicAdd(&orow[j * 8 + 0], acc[i][j][half * 2 + 0] * wgt);
                        atomicAdd(&orow[j * 8 + 1], acc[i][j][half * 2 + 1] * wgt);
                    }
                }
            }
        }
    }
#undef S2_LOAD
#undef S2_STORE
}

// ---------------- launch ----------------
extern "C" void kernel_launch(void* const* d_in, const int* in_sizes, int n_in,
                              void* d_out, int out_size) {
    const float* x   = (const float*)d_in[0];
    const float* gw  = (const float*)d_in[1];
    const float* gb  = (const float*)d_in[2];
    const float* w1  = (const float*)d_in[3];
    const float* w2  = (const float*)d_in[4];
    const float* w3  = (const float*)d_in[5];
    const float* sw1 = (const float*)d_in[6];
    const float* sw2 = (const float*)d_in[7];
    const float* sw3 = (const float*)d_in[8];
    float* out = (float*)d_out;

    const int s1_smem = (2 * ABUF_W + 4 * S1B_W) * 4;   // 61440 bytes
    const int s2_smem = (2 * ABUF_W + 2 * S2B_W) * 4;   // 61440 bytes
    cudaFuncSetAttribute(stage1_mma, cudaFuncAttributeMaxDynamicSharedMemorySize, s1_smem);
    cudaFuncSetAttribute(stage2_mma<true >, cudaFuncAttributeMaxDynamicSharedMemorySize, s2_smem);
    cudaFuncSetAttribute(stage2_mma<false>, cudaFuncAttributeMaxDynamicSharedMemorySize, s2_smem);

    zero_counts_kernel<<<1, 32>>>();
    gate_kernel<<<T_TOKENS / 8, 256>>>(x, gw, gb);
    stage1_mma<<<dim3((NE + 1) * 128, INTER / 128), 256, s1_smem>>>(x, w1, w3, sw1, sw3);
    stage2_mma<true ><<<dim3(T_TOKENS / 128, DIM / 256), 256, s2_smem>>>(w2, sw2, out);
    stage2_mma<false><<<dim3(NE * 128,       DIM / 256), 256, s2_smem>>>(w2, sw2, out);
}